// round 2
// baseline (speedup 1.0000x reference)
#include <cuda_runtime.h>
#include <cuda_bf16.h>

#define Bz 8
#define Tt 12
#define NN 512
#define FIN 32
#define FOUT 64

// Scratch (device globals; no allocation allowed)
__device__ float g_xtA[Bz*Tt*NN*FIN];          // 6.3 MB
__device__ float g_xtB[Bz*Tt*NN*FIN];          // 6.3 MB
__device__ float g_W[(long)Bz*Tt*NN*NN];       // 100.7 MB
__device__ float g_agg[Bz*Tt*NN*FIN];          // 6.3 MB

// ---------------------------------------------------------------------------
// K0: transpose x (B,N,T,F) -> xt (B,T,N,F)
__global__ __launch_bounds__(256) void k_transpose(const float* __restrict__ x,
                                                   float* __restrict__ xt) {
    int idx = blockIdx.x * blockDim.x + threadIdx.x;
    if (idx >= Bz*Tt*NN*FIN) return;
    int f = idx & (FIN-1);
    int n = (idx >> 5) & (NN-1);
    int t = (idx / (FIN*NN)) % Tt;
    int b = idx / (FIN*NN*Tt);
    xt[idx] = x[(((long)b*NN + n)*Tt + t)*FIN + f];
}

// ---------------------------------------------------------------------------
// K1: per (b,t): scores = X X^T / sqrt(F), row softmax, weight
//     W[m,n] = phase[b,t,m,n] * (adj[m,n]) * softmax_row_m[n] * invSqrtF
// grid: (mtile=8, tcount, b=8), 256 threads, 64 rows per CTA, 8 rows/warp
__global__ __launch_bounds__(256) void k_scores(const float* __restrict__ xsrc,
                                                const float* __restrict__ phase,
                                                const float* __restrict__ adj,
                                                float* __restrict__ Wg,
                                                int t_base) {
    extern __shared__ float Xs[];  // [512][33] padded
    const int b = blockIdx.z;
    const int t = blockIdx.y + t_base;
    const int m0 = blockIdx.x * 64;
    const long bt = (long)(b*Tt + t);
    const float* Xrow = xsrc + bt*NN*FIN;

    for (int i = threadIdx.x; i < NN*FIN; i += 256) {
        int n = i >> 5, f = i & 31;
        Xs[n*33 + f] = Xrow[i];
    }
    __syncthreads();

    const int warp = threadIdx.x >> 5;
    const int lane = threadIdx.x & 31;
    const float inv_sqrt_f = 0.17677669529663687f;  // 1/sqrt(32)

    for (int r = 0; r < 8; ++r) {
        const int m = m0 + warp*8 + r;
        float xm[FIN];
        #pragma unroll
        for (int f = 0; f < FIN; ++f) xm[f] = Xs[m*33 + f];

        float s[16];
        #pragma unroll
        for (int k = 0; k < 16; ++k) {
            const float* xn = &Xs[(k*32 + lane)*33];
            float acc = 0.f;
            #pragma unroll
            for (int f = 0; f < FIN; ++f) acc += xm[f] * xn[f];
            s[k] = acc * inv_sqrt_f;
        }
        // row max
        float mx = s[0];
        #pragma unroll
        for (int k = 1; k < 16; ++k) mx = fmaxf(mx, s[k]);
        #pragma unroll
        for (int o = 16; o > 0; o >>= 1) mx = fmaxf(mx, __shfl_xor_sync(0xffffffffu, mx, o));
        // exp + sum
        float sum = 0.f;
        #pragma unroll
        for (int k = 0; k < 16; ++k) { s[k] = __expf(s[k] - mx); sum += s[k]; }
        #pragma unroll
        for (int o = 16; o > 0; o >>= 1) sum += __shfl_xor_sync(0xffffffffu, sum, o);
        const float rs = inv_sqrt_f / sum;

        const float* ph = phase + (bt*NN + m)*NN;
        float* wr = Wg + (bt*NN + m)*NN;
        if (adj) {
            const float* ar = adj + m*NN;
            #pragma unroll
            for (int k = 0; k < 16; ++k) {
                int n = k*32 + lane;
                wr[n] = ph[n] * ar[n] * s[k] * rs;
            }
        } else {
            #pragma unroll
            for (int k = 0; k < 16; ++k) {
                int n = k*32 + lane;
                wr[n] = ph[n] * s[k] * rs;
            }
        }
    }
}

// ---------------------------------------------------------------------------
// K2: out[n,f] = sum_m W[m,n] * Xp[m,f]   (apply, transposed weight)
// body mode: Xp = xsrc at time t-1; dst[n] = mask[n]*xsrc[t,n] + (1-mask)*out
//            t==0 blocks just copy through.
// final mode: Xp = xsrc at time t; dst = agg (raw write).
// grid: (ntile=4, t=12, b=8), 512 threads
__global__ __launch_bounds__(512) void k_apply(const float* __restrict__ Wg,
                                               const float* __restrict__ xsrc,
                                               float* __restrict__ dst,
                                               const float* __restrict__ mask,
                                               int final_mode) {
    extern __shared__ float sm[];
    float* Xp = sm;               // 512*32
    float* Wt = sm + NN*FIN;      // 32*128
    const int b = blockIdx.z, t = blockIdx.y;
    const int n0 = blockIdx.x * 128;
    const long bt = (long)(b*Tt + t);

    if (!final_mode && t == 0) {
        const float* s = xsrc + (bt*NN + n0)*FIN;
        float* d = dst + (bt*NN + n0)*FIN;
        for (int i = threadIdx.x; i < 128*FIN; i += 512) d[i] = s[i];
        return;
    }

    const int tsrc = final_mode ? t : (t - 1);
    const float* Xrow = xsrc + ((long)(b*Tt + tsrc))*NN*FIN;
    for (int i = threadIdx.x; i < NN*FIN; i += 512) Xp[i] = Xrow[i];

    // mapping: lanes cover f-groups first -> coalesced epilogue stores
    const int fg = threadIdx.x & 3;
    const int nl = threadIdx.x >> 2;     // 0..127
    const int f0 = fg * 8;

    float acc[8] = {0,0,0,0,0,0,0,0};

    for (int m0 = 0; m0 < NN; m0 += 32) {
        __syncthreads();
        const float* wsrc = Wg + (bt*NN + m0)*NN + n0;
        #pragma unroll
        for (int j = 0; j < 8; ++j) {
            int e = threadIdx.x + j*512;
            int r = e >> 7, c = e & 127;
            Wt[r*128 + c] = wsrc[r*NN + c];
        }
        __syncthreads();
        #pragma unroll
        for (int mm = 0; mm < 32; ++mm) {
            float w = Wt[mm*128 + nl];
            const float4* xr = (const float4*)&Xp[(m0+mm)*FIN + f0];
            float4 a0 = xr[0], a1 = xr[1];
            acc[0] += w*a0.x; acc[1] += w*a0.y; acc[2] += w*a0.z; acc[3] += w*a0.w;
            acc[4] += w*a1.x; acc[5] += w*a1.y; acc[6] += w*a1.z; acc[7] += w*a1.w;
        }
    }

    const int n = n0 + nl;
    float* d = dst + (bt*NN + n)*FIN + f0;
    if (final_mode) {
        #pragma unroll
        for (int j = 0; j < 8; ++j) d[j] = acc[j];
    } else {
        float mk = mask[n];
        const float* o = xsrc + (bt*NN + n)*FIN + f0;
        #pragma unroll
        for (int j = 0; j < 8; ++j) d[j] = mk*o[j] + (1.f - mk)*acc[j];
    }
}

// ---------------------------------------------------------------------------
// K3: out[b,n,t,o] = relu(sum_f agg[b,t,n,f] * theta[f,o])
// grid: (t=12, b=8), 512 threads
__global__ __launch_bounds__(512) void k_out(const float* __restrict__ agg,
                                             const float* __restrict__ theta,
                                             float* __restrict__ out) {
    extern __shared__ float sm[];
    float* th = sm;              // 32*64
    float* ag = sm + FIN*FOUT;   // 512*32
    const int b = blockIdx.y, t = blockIdx.x;
    const long base = ((long)(b*Tt + t))*NN*FIN;
    for (int i = threadIdx.x; i < FIN*FOUT; i += 512) th[i] = theta[i];
    for (int i = threadIdx.x; i < NN*FIN; i += 512) ag[i] = agg[base + i];
    __syncthreads();

    const int o = threadIdx.x & 63;
    const int ng = threadIdx.x >> 6;  // 0..7
    for (int nb = 0; nb < 64; ++nb) {
        int n = nb*8 + ng;
        float acc = 0.f;
        #pragma unroll
        for (int f = 0; f < FIN; ++f) acc += ag[n*FIN + f] * th[f*FOUT + o];
        out[(((long)b*NN + n)*Tt + t)*FOUT + o] = fmaxf(acc, 0.f);
    }
}

// ---------------------------------------------------------------------------
extern "C" void kernel_launch(void* const* d_in, const int* in_sizes, int n_in,
                              void* d_out, int out_size) {
    const float* x     = (const float*)d_in[0];
    const float* phase = (const float*)d_in[1];
    const float* adj   = (const float*)d_in[2];
    const float* mask  = (const float*)d_in[3];
    const float* theta = (const float*)d_in[4];
    float* out = (float*)d_out;

    float *xtA, *xtB, *Wg, *agg;
    cudaGetSymbolAddress((void**)&xtA, g_xtA);
    cudaGetSymbolAddress((void**)&xtB, g_xtB);
    cudaGetSymbolAddress((void**)&Wg,  g_W);
    cudaGetSymbolAddress((void**)&agg, g_agg);

    const int SM1 = 512*33*4;                  // 67584
    const int SM2 = (NN*FIN + 32*128)*4;       // 81920
    const int SM3 = (FIN*FOUT + NN*FIN)*4;     // 73728
    cudaFuncSetAttribute(k_scores, cudaFuncAttributeMaxDynamicSharedMemorySize, SM1);
    cudaFuncSetAttribute(k_apply,  cudaFuncAttributeMaxDynamicSharedMemorySize, SM2);
    cudaFuncSetAttribute(k_out,    cudaFuncAttributeMaxDynamicSharedMemorySize, SM3);

    k_transpose<<<(Bz*Tt*NN*FIN + 255)/256, 256>>>(x, xtA);

    float* src = xtA;
    float* dst = xtB;
    for (int it = 0; it < Tt - 1; ++it) {
        // body: weights for t=1..11
        k_scores<<<dim3(8, Tt-1, Bz), 256, SM1>>>(src, phase, nullptr, Wg, 1);
        k_apply <<<dim3(4, Tt,   Bz), 512, SM2>>>(Wg, src, dst, mask, 0);
        float* tmp = src; src = dst; dst = tmp;
    }
    // final aggregation
    k_scores<<<dim3(8, Tt, Bz), 256, SM1>>>(src, phase, adj, Wg, 0);
    k_apply <<<dim3(4, Tt, Bz), 512, SM2>>>(Wg, src, agg, mask, 1);
    k_out   <<<dim3(Tt, Bz),    512, SM3>>>(agg, theta, out);
}

// round 3
// speedup vs baseline: 2.7328x; 2.7328x over previous
#include <cuda_runtime.h>
#include <cuda_bf16.h>

#define Bz 8
#define Tt 12
#define NN 512
#define FIN 32
#define FOUT 64
#define CH 128          // m-chunk rows per CTA
#define XSTRIDE 36      // padded row stride for Xt (16B aligned, reduces xn-load conflicts)

// Scratch (device globals; no allocation allowed)
__device__ float g_xtA[Bz*Tt*NN*FIN];                // 6.3 MB
__device__ float g_xtB[Bz*Tt*NN*FIN];                // 6.3 MB
__device__ float g_part[4L*Bz*Tt*NN*FIN];            // 25 MB partial outputs

// ---------------------------------------------------------------------------
// K0: transpose x (B,N,T,F) -> xt (B,T,N,F)
__global__ __launch_bounds__(256) void k_transpose(const float* __restrict__ x,
                                                   float* __restrict__ xt) {
    int idx = blockIdx.x * blockDim.x + threadIdx.x;
    if (idx >= Bz*Tt*NN*FIN) return;
    int f = idx & (FIN-1);
    int n = (idx >> 5) & (NN-1);
    int t = (idx / (FIN*NN)) % Tt;
    int b = idx / (FIN*NN*Tt);
    xt[idx] = x[(((long)b*NN + n)*Tt + t)*FIN + f];
}

// ---------------------------------------------------------------------------
// Fused: per (b, t, chunk c): for m in [c*CH, c*CH+CH):
//   s[m,n] = X(t)[m]·X(t)[n] / sqrt(F)   -> softmax over n
//   w[m,n] = phase[b,t,m,n] * (adj[m,n]) * softmax * invSqrtF
//   partial[c][bt][n][f] = sum_{m in chunk} w[m,n] * Xp[m,f]
// where Xp = X(t-1) (body) or X(t) (final, adj != null).
// block = 512 threads (16 warps). Warp w owns n-block [32w, 32w+32) in regs.
__global__ __launch_bounds__(512) void k_fused(const float* __restrict__ xsrc,
                                               const float* __restrict__ phase,
                                               const float* __restrict__ adj,
                                               float* __restrict__ part,
                                               int t_base) {
    extern __shared__ float sm[];
    float* Xt = sm;                       // 512 x 36
    float* Xp = sm + NN*XSTRIDE;          // 128 x 32
    float* S  = Xp + CH*FIN;              // 32 x 512

    const int b = blockIdx.z;
    const int t = blockIdx.y + t_base;
    const int c = blockIdx.x;
    const int bt = b*Tt + t;
    const int m_base = c*CH;
    const int tid = threadIdx.x, warp = tid >> 5, lane = tid & 31;

    // load X(t) full, padded stride
    const float* Xg = xsrc + (long)bt*NN*FIN;
    for (int i = tid; i < NN*FIN; i += 512)
        Xt[(i >> 5)*XSTRIDE + (i & 31)] = Xg[i];
    // load Xprev chunk rows, dense stride 32
    const int tsrc = adj ? t : t - 1;
    const float* Xpg = xsrc + ((long)(b*Tt + tsrc)*NN + m_base)*FIN;
    for (int i = tid; i < CH*FIN; i += 512) Xp[i] = Xpg[i];
    __syncthreads();

    // xn registers: this lane's n-column (n = warp*32+lane)
    float xn[FIN];
    {
        const float* xr = &Xt[(warp*32 + lane)*XSTRIDE];
        #pragma unroll
        for (int f = 0; f < FIN; ++f) xn[f] = xr[f];
    }
    float acc[FIN];
    #pragma unroll
    for (int f = 0; f < FIN; ++f) acc[f] = 0.f;

    const float inv_sqrt_f = 0.17677669529663687f;  // 1/sqrt(32)

    for (int sc = 0; sc < CH/32; ++sc) {
        const int ms = m_base + sc*32;

        // ---- score tile: rows ms..ms+31 vs this warp's n-block ----
        #pragma unroll 4
        for (int mm = 0; mm < 32; ++mm) {
            const float4* xm4 = (const float4*)&Xt[(ms + mm)*XSTRIDE];
            float s = 0.f;
            #pragma unroll
            for (int j = 0; j < 8; ++j) {
                float4 v = xm4[j];   // broadcast across warp
                s += v.x*xn[4*j] + v.y*xn[4*j+1] + v.z*xn[4*j+2] + v.w*xn[4*j+3];
            }
            S[mm*NN + warp*32 + lane] = s * inv_sqrt_f;
        }
        __syncthreads();

        // ---- softmax + phase weight: 2 rows per warp ----
        #pragma unroll
        for (int rr = 0; rr < 2; ++rr) {
            const int mm = warp*2 + rr;
            const int m = ms + mm;
            float v[16];
            #pragma unroll
            for (int k = 0; k < 16; ++k) v[k] = S[mm*NN + k*32 + lane];
            float mx = v[0];
            #pragma unroll
            for (int k = 1; k < 16; ++k) mx = fmaxf(mx, v[k]);
            #pragma unroll
            for (int o = 16; o; o >>= 1) mx = fmaxf(mx, __shfl_xor_sync(0xffffffffu, mx, o));
            float sum = 0.f;
            #pragma unroll
            for (int k = 0; k < 16; ++k) { v[k] = __expf(v[k] - mx); sum += v[k]; }
            #pragma unroll
            for (int o = 16; o; o >>= 1) sum += __shfl_xor_sync(0xffffffffu, sum, o);
            const float rs = inv_sqrt_f / sum;

            const float* ph = phase + ((long)bt*NN + m)*NN;
            if (adj) {
                const float* ar = adj + m*NN;
                #pragma unroll
                for (int k = 0; k < 16; ++k) {
                    int n = k*32 + lane;
                    S[mm*NN + n] = ph[n] * ar[n] * v[k] * rs;
                }
            } else {
                #pragma unroll
                for (int k = 0; k < 16; ++k) {
                    int n = k*32 + lane;
                    S[mm*NN + n] = ph[n] * v[k] * rs;
                }
            }
        }
        __syncthreads();

        // ---- apply: thread <-> n = tid; acc[f] += w[m,n] * Xp[m,f] ----
        #pragma unroll 4
        for (int mm = 0; mm < 32; ++mm) {
            float w = S[mm*NN + tid];
            const float4* xp4 = (const float4*)&Xp[(sc*32 + mm)*FIN];
            #pragma unroll
            for (int j = 0; j < 8; ++j) {
                float4 v = xp4[j];   // broadcast
                acc[4*j]   += w*v.x; acc[4*j+1] += w*v.y;
                acc[4*j+2] += w*v.z; acc[4*j+3] += w*v.w;
            }
        }
        __syncthreads();
    }

    float4* dst = (float4*)(part + (((long)c*(Bz*Tt) + bt)*NN + tid)*FIN);
    #pragma unroll
    for (int j = 0; j < 8; ++j)
        dst[j] = make_float4(acc[4*j], acc[4*j+1], acc[4*j+2], acc[4*j+3]);
}

// ---------------------------------------------------------------------------
// Blend: x_next(t) = mask*x_cur(t) + (1-mask)*sum_c partial[c]   (t>=1)
//        x_next(0) = x_cur(0)
__global__ __launch_bounds__(512) void k_blend(const float* __restrict__ part,
                                               const float* __restrict__ xsrc,
                                               float* __restrict__ dst,
                                               const float* __restrict__ mask) {
    const int b = blockIdx.y, t = blockIdx.x;
    const long base = (long)(b*Tt + t)*NN*FIN;
    if (t == 0) {
        const float4* s = (const float4*)(xsrc + base);
        float4* d = (float4*)(dst + base);
        for (int i = threadIdx.x; i < NN*FIN/4; i += 512) d[i] = s[i];
        return;
    }
    const long P = (long)(Bz*Tt)*NN*FIN;
    const float4* p0 = (const float4*)(part + base);
    const float4* p1 = (const float4*)(part + P + base);
    const float4* p2 = (const float4*)(part + 2*P + base);
    const float4* p3 = (const float4*)(part + 3*P + base);
    const float4* xs = (const float4*)(xsrc + base);
    float4* d = (float4*)(dst + base);
    for (int i = threadIdx.x; i < NN*FIN/4; i += 512) {
        float mk = mask[i >> 3];
        float om = 1.f - mk;
        float4 a = p0[i], bb = p1[i], cc = p2[i], e = p3[i], x = xs[i];
        float4 r;
        r.x = mk*x.x + om*(a.x + bb.x + cc.x + e.x);
        r.y = mk*x.y + om*(a.y + bb.y + cc.y + e.y);
        r.z = mk*x.z + om*(a.z + bb.z + cc.z + e.z);
        r.w = mk*x.w + om*(a.w + bb.w + cc.w + e.w);
        d[i] = r;
    }
}

// ---------------------------------------------------------------------------
// K3: out[b,n,t,o] = relu(sum_f agg[b,t,n,f] * theta[f,o]), agg = sum of partials
__global__ __launch_bounds__(512) void k_out(const float* __restrict__ part,
                                             const float* __restrict__ theta,
                                             float* __restrict__ out) {
    extern __shared__ float sm[];
    float* th = sm;              // 32*64
    float* ag = sm + FIN*FOUT;   // 512*32
    const int b = blockIdx.y, t = blockIdx.x;
    const long base = (long)(b*Tt + t)*NN*FIN;
    const long P = (long)(Bz*Tt)*NN*FIN;
    for (int i = threadIdx.x; i < FIN*FOUT; i += 512) th[i] = theta[i];
    for (int i = threadIdx.x; i < NN*FIN; i += 512)
        ag[i] = part[base+i] + part[P+base+i] + part[2*P+base+i] + part[3*P+base+i];
    __syncthreads();

    const int o = threadIdx.x & 63;
    const int ng = threadIdx.x >> 6;  // 0..7
    for (int nb = 0; nb < 64; ++nb) {
        int n = nb*8 + ng;
        float acc = 0.f;
        #pragma unroll
        for (int f = 0; f < FIN; ++f) acc += ag[n*FIN + f] * th[f*FOUT + o];
        out[(((long)b*NN + n)*Tt + t)*FOUT + o] = fmaxf(acc, 0.f);
    }
}

// ---------------------------------------------------------------------------
extern "C" void kernel_launch(void* const* d_in, const int* in_sizes, int n_in,
                              void* d_out, int out_size) {
    const float* x     = (const float*)d_in[0];
    const float* phase = (const float*)d_in[1];
    const float* adj   = (const float*)d_in[2];
    const float* mask  = (const float*)d_in[3];
    const float* theta = (const float*)d_in[4];
    float* out = (float*)d_out;

    float *xtA, *xtB, *partg;
    cudaGetSymbolAddress((void**)&xtA, g_xtA);
    cudaGetSymbolAddress((void**)&xtB, g_xtB);
    cudaGetSymbolAddress((void**)&partg, g_part);

    const int SMF = (NN*XSTRIDE + CH*FIN + 32*NN)*4;   // 155648 B
    const int SM3 = (FIN*FOUT + NN*FIN)*4;             // 73728 B
    cudaFuncSetAttribute(k_fused, cudaFuncAttributeMaxDynamicSharedMemorySize, SMF);
    cudaFuncSetAttribute(k_out,   cudaFuncAttributeMaxDynamicSharedMemorySize, SM3);

    k_transpose<<<(Bz*Tt*NN*FIN + 255)/256, 256>>>(x, xtA);

    float* src = xtA;
    float* dst = xtB;
    for (int it = 0; it < Tt - 1; ++it) {
        k_fused<<<dim3(4, Tt-1, Bz), 512, SMF>>>(src, phase, nullptr, partg, 1);
        k_blend<<<dim3(Tt, Bz), 512>>>(partg, src, dst, mask);
        float* tmp = src; src = dst; dst = tmp;
    }
    k_fused<<<dim3(4, Tt, Bz), 512, SMF>>>(src, phase, adj, partg, 0);
    k_out<<<dim3(Tt, Bz), 512, SM3>>>(partg, theta, out);
}